// round 6
// baseline (speedup 1.0000x reference)
#include <cuda_runtime.h>
#include <cuda_bf16.h>
#include <math.h>
#include <stdint.h>

// Problem constants
#define L_SEQ   2048
#define DM      1024
#define DI      1024
#define DTR     64
#define DS      16
#define PROJ    (DTR + 2 * DI * DS)   // 32832
#define NPAD    32896                 // 257 * 128
#define KDIM    1024

// -------- scratch (static device globals; no allocation) --------
__device__ float g_dbc[(size_t)L_SEQ * PROJ];
__device__ float g_delta[(size_t)L_SEQ * DI];
__device__ __nv_bfloat16 g_xh[(size_t)L_SEQ * DM];
__device__ __nv_bfloat16 g_xl[(size_t)L_SEQ * DM];
__device__ __nv_bfloat16 g_wh[(size_t)NPAD * DM];
__device__ __nv_bfloat16 g_wl[(size_t)NPAD * DM];
__device__ __nv_bfloat16 g_yh[(size_t)L_SEQ * DI];
__device__ __nv_bfloat16 g_yl[(size_t)L_SEQ * DI];
__device__ __nv_bfloat16 g_woh[(size_t)DM * DI];
__device__ __nv_bfloat16 g_wol[(size_t)DM * DI];

// ============================================================================
// helpers
// ============================================================================
__device__ __forceinline__ uint32_t smem_u32(const void* p) {
    uint32_t a;
    asm("{ .reg .u64 t; cvta.to.shared.u64 t, %1; cvt.u32.u64 %0, t; }" : "=r"(a) : "l"(p));
    return a;
}
__device__ __forceinline__ uint32_t swz128(uint32_t o) { return o ^ ((o >> 3) & 0x70); }

__device__ __forceinline__ void cp_async16(uint32_t dst, const void* src) {
    asm volatile("cp.async.cg.shared.global [%0], [%1], 16;" :: "r"(dst), "l"(src));
}
#define CP_COMMIT() asm volatile("cp.async.commit_group;" ::: "memory")
#define CP_WAIT(n)  asm volatile("cp.async.wait_group %0;" :: "n"(n) : "memory")

__device__ __forceinline__ void ldsm4(uint32_t* r, uint32_t addr) {
    asm volatile("ldmatrix.sync.aligned.m8n8.x4.shared.b16 {%0,%1,%2,%3}, [%4];"
        : "=r"(r[0]), "=r"(r[1]), "=r"(r[2]), "=r"(r[3]) : "r"(addr));
}
__device__ __forceinline__ void mma_bf16(float* d, const uint32_t* a, const uint32_t* b) {
    asm volatile(
        "mma.sync.aligned.m16n8k16.row.col.f32.bf16.bf16.f32 "
        "{%0,%1,%2,%3}, {%4,%5,%6,%7}, {%8,%9}, {%0,%1,%2,%3};"
        : "+f"(d[0]), "+f"(d[1]), "+f"(d[2]), "+f"(d[3])
        : "r"(a[0]), "r"(a[1]), "r"(a[2]), "r"(a[3]), "r"(b[0]), "r"(b[1]));
}

// ============================================================================
// Split conversion: hi = bf16(v), lo = bf16(v - hi). Zero-pad beyond n_valid.
// ============================================================================
__global__ __launch_bounds__(256) void split_kernel(
    const float* __restrict__ src, __nv_bfloat16* __restrict__ hi,
    __nv_bfloat16* __restrict__ lo, size_t n_valid, size_t n_total)
{
    size_t i = ((size_t)blockIdx.x * 256 + threadIdx.x) * 4;
    if (i >= n_total) return;
    float4 v = make_float4(0.f, 0.f, 0.f, 0.f);
    if (i < n_valid) v = *(const float4*)(src + i);
    __nv_bfloat16 h0 = __float2bfloat16_rn(v.x);
    __nv_bfloat16 h1 = __float2bfloat16_rn(v.y);
    __nv_bfloat16 h2 = __float2bfloat16_rn(v.z);
    __nv_bfloat16 h3 = __float2bfloat16_rn(v.w);
    __nv_bfloat16 l0 = __float2bfloat16_rn(v.x - __bfloat162float(h0));
    __nv_bfloat16 l1 = __float2bfloat16_rn(v.y - __bfloat162float(h1));
    __nv_bfloat16 l2 = __float2bfloat16_rn(v.z - __bfloat162float(h2));
    __nv_bfloat16 l3 = __float2bfloat16_rn(v.w - __bfloat162float(h3));
    *(__nv_bfloat162*)(hi + i)     = __nv_bfloat162(h0, h1);
    *(__nv_bfloat162*)(hi + i + 2) = __nv_bfloat162(h2, h3);
    *(__nv_bfloat162*)(lo + i)     = __nv_bfloat162(l0, l1);
    *(__nv_bfloat162*)(lo + i + 2) = __nv_bfloat162(l2, l3);
}

// ============================================================================
// Split-bf16 tensor-core GEMM via mma.sync.
// CTA tile 256x128, 256 threads (8 warps, grid 4x2, warp tile 64x64),
// BK=32, 4-stage cp.async pipeline (48 KB/stage), prefetch distance 3.
// 1 CTA/SM, 256 regs/thread (acc = 128 regs).
// ============================================================================
#define BM      256
#define BN      128
#define ATILE   16384               // 256 rows x 64 B (one of Ah/Al)
#define BTILE   8192                // 128 rows x 64 B (one of Bh/Bl)
#define AH_OFF  0
#define AL_OFF  16384
#define BH_OFF  32768
#define BL_OFF  40960
#define STAGE_B 49152               // 48 KB
#define NSTAGE  4
#define SMEM_MMA_TOTAL (NSTAGE * STAGE_B)    // 192 KB
#define NKC     (KDIM / 32)         // 32 k-iters

__global__ __launch_bounds__(256, 1) void gemm_mma(
    const __nv_bfloat16* __restrict__ Ah, const __nv_bfloat16* __restrict__ Al,
    const __nv_bfloat16* __restrict__ Bh, const __nv_bfloat16* __restrict__ Bl,
    float* __restrict__ C, int ldc, int nvalid)
{
    extern __shared__ char smem[];
    const uint32_t sbase = smem_u32(smem);
    const int tid = threadIdx.x;
    const int wid = tid >> 5, lane = tid & 31;
    const int wm = wid >> 1, wn = wid & 1;       // warp grid 4 (m) x 2 (n)

    const int m0 = blockIdx.x * BM;
    const int n0 = blockIdx.y * BN;

    float acc[4][8][4];
    #pragma unroll
    for (int i = 0; i < 4; i++)
        #pragma unroll
        for (int j = 0; j < 8; j++)
            #pragma unroll
            for (int q = 0; q < 4; q++) acc[i][j][q] = 0.f;

    auto issue = [&](int kc) {
        if (kc < NKC) {
            const uint32_t soff = sbase + (kc & 3) * STAGE_B;
            // A tiles: 1024 16B-chunks per operand (256 rows x 4)
            #pragma unroll
            for (int j = 0; j < 4; j++) {
                const int q = tid * 4 + j;         // 0..1023
                const int row = q >> 2, c = q & 3;
                const uint32_t so = swz128((uint32_t)(row * 64 + c * 16));
                const size_t ga = (size_t)(m0 + row) * KDIM + (size_t)kc * 32 + c * 8;
                cp_async16(soff + AH_OFF + so, Ah + ga);
                cp_async16(soff + AL_OFF + so, Al + ga);
            }
            // B tiles: 512 chunks per operand (128 rows x 4)
            #pragma unroll
            for (int j = 0; j < 2; j++) {
                const int q = tid * 2 + j;         // 0..511
                const int row = q >> 2, c = q & 3;
                const uint32_t so = swz128((uint32_t)(row * 64 + c * 16));
                const size_t gb = (size_t)(n0 + row) * KDIM + (size_t)kc * 32 + c * 8;
                cp_async16(soff + BH_OFF + so, Bh + gb);
                cp_async16(soff + BL_OFF + so, Bl + gb);
            }
        }
        CP_COMMIT();
    };

    issue(0);
    issue(1);
    issue(2);

    #pragma unroll 1
    for (int kc = 0; kc < NKC; kc++) {
        CP_WAIT(2);                 // group kc landed (trailing empty commits keep numbering)
        __syncthreads();
        issue(kc + 3);              // refill buffer consumed at iter kc-1

        const uint32_t sA = sbase + (kc & 3) * STAGE_B;

        #pragma unroll
        for (int ks = 0; ks < 2; ks++) {
            uint32_t bh[8][2], bl[8][2];
            #pragma unroll
            for (int p = 0; p < 4; p++) {
                const int rowb = wn * 64 + p * 16 + ((lane >> 4) << 3) + (lane & 7);
                const int chb  = ks * 2 + ((lane >> 3) & 1);
                const uint32_t ob = swz128((uint32_t)(rowb * 64 + chb * 16));
                ldsm4(&bh[p * 2][0], sA + BH_OFF + ob);
                ldsm4(&bl[p * 2][0], sA + BL_OFF + ob);
            }
            #pragma unroll
            for (int mf = 0; mf < 4; mf++) {
                const int rowa = wm * 64 + mf * 16 + (lane & 15);
                const int cha  = ks * 2 + (lane >> 4);
                const uint32_t oa = swz128((uint32_t)(rowa * 64 + cha * 16));
                uint32_t ah[4], al[4];
                ldsm4(ah, sA + AH_OFF + oa);
                ldsm4(al, sA + AL_OFF + oa);
                #pragma unroll
                for (int nf = 0; nf < 8; nf++) mma_bf16(acc[mf][nf], ah, bh[nf]);
                #pragma unroll
                for (int nf = 0; nf < 8; nf++) mma_bf16(acc[mf][nf], al, bh[nf]);
                #pragma unroll
                for (int nf = 0; nf < 8; nf++) mma_bf16(acc[mf][nf], ah, bl[nf]);
            }
        }
    }

    // ---- epilogue ----
    const int g = lane >> 2, t4 = lane & 3;
    #pragma unroll
    for (int mf = 0; mf < 4; mf++) {
        #pragma unroll
        for (int nf = 0; nf < 8; nf++) {
            const int m = m0 + wm * 64 + mf * 16 + g;
            const int n = n0 + wn * 64 + nf * 8 + t4 * 2;
            if (n < nvalid) {
                *(float2*)(C + (size_t)m * ldc + n) =
                    make_float2(acc[mf][nf][0], acc[mf][nf][1]);
                *(float2*)(C + (size_t)(m + 8) * ldc + n) =
                    make_float2(acc[mf][nf][2], acc[mf][nf][3]);
            }
        }
    }
}

// ============================================================================
// delta[t,d] = softplus(dbc[t,0:64] · W_delta[d,:])
// ============================================================================
__global__ __launch_bounds__(128) void delta_kernel(const float* __restrict__ W_delta)
{
    __shared__ float s_dl[8][64];
    __shared__ float s_wT[64][129];
    const int tid = threadIdx.x;
    const int t0 = blockIdx.x * 8;
    const int d0 = blockIdx.y * 128;

    for (int i = tid; i < 8 * 64; i += 128) {
        int t = i >> 6, k = i & 63;
        s_dl[t][k] = g_dbc[(size_t)(t0 + t) * PROJ + k];
    }
    for (int i = tid; i < 128 * 64; i += 128) {
        int d = i >> 6, k = i & 63;
        s_wT[k][d] = W_delta[(size_t)(d0 + d) * DTR + k];
    }
    __syncthreads();

    float accv[8];
    #pragma unroll
    for (int t = 0; t < 8; t++) accv[t] = 0.f;
    #pragma unroll 8
    for (int k = 0; k < 64; k++) {
        float w = s_wT[k][tid];
        #pragma unroll
        for (int t = 0; t < 8; t++) accv[t] = fmaf(s_dl[t][k], w, accv[t]);
    }
    #pragma unroll
    for (int t = 0; t < 8; t++) {
        float z = accv[t];
        float sp = fmaxf(z, 0.f) + log1pf(__expf(-fabsf(z)));
        g_delta[(size_t)(t0 + t) * DI + d0 + tid] = sp;
    }
}

// ============================================================================
// Selective scan: 1 thread per (d, s). 128 blocks x 128 threads, prefetch 8.
// Writes y directly as split bf16 (yh, yl) for the output GEMM.
// ============================================================================
__global__ __launch_bounds__(128) void scan_kernel(
    const float* __restrict__ x, const float* __restrict__ A_log,
    const float* __restrict__ Dv)
{
    const int g = blockIdx.x * 128 + threadIdx.x;    // 0..16383
    const int d = g >> 4, s = g & 15;
    const float a = -expf(A_log[d * DS + s]);
    const float Dd = Dv[d];
    const float* bp = g_dbc + DTR + d * DS + s;
    const float* cp = bp + DI * DS;

    float Bpf[8], Cpf[8], Tpf[8], Xpf[8];
    #pragma unroll
    for (int i = 0; i < 8; i++) {
        Bpf[i] = bp[(size_t)i * PROJ];
        Cpf[i] = cp[(size_t)i * PROJ];
        Tpf[i] = g_delta[(size_t)i * DI + d];
        Xpf[i] = x[(size_t)i * DI + d];
    }
    float h = 0.f;
    #pragma unroll 8
    for (int t = 0; t < L_SEQ; t++) {
        const int sl = t & 7;
        const float dt = Tpf[sl], xt = Xpf[sl], Bv = Bpf[sl], Cv = Cpf[sl];
        const int tn = t + 8;
        if (tn < L_SEQ) {
            Bpf[sl] = bp[(size_t)tn * PROJ];
            Cpf[sl] = cp[(size_t)tn * PROJ];
            Tpf[sl] = g_delta[(size_t)tn * DI + d];
            Xpf[sl] = x[(size_t)tn * DI + d];
        }
        h = fmaf(__expf(dt * a), h, dt * xt * Bv);
        float yv = h * Cv;
        yv += __shfl_xor_sync(0xffffffffu, yv, 1);
        yv += __shfl_xor_sync(0xffffffffu, yv, 2);
        yv += __shfl_xor_sync(0xffffffffu, yv, 4);
        yv += __shfl_xor_sync(0xffffffffu, yv, 8);
        if (s == 0) {
            float yfull = fmaf(xt, Dd, yv);
            __nv_bfloat16 yh = __float2bfloat16_rn(yfull);
            __nv_bfloat16 yl = __float2bfloat16_rn(yfull - __bfloat162float(yh));
            g_yh[(size_t)t * DI + d] = yh;
            g_yl[(size_t)t * DI + d] = yl;
        }
    }
}

// ============================================================================
// Launch
// ============================================================================
extern "C" void kernel_launch(void* const* d_in, const int* in_sizes, int n_in,
                              void* d_out, int out_size)
{
    const float* x       = (const float*)d_in[0];
    const float* W_in    = (const float*)d_in[1];
    const float* W_delta = (const float*)d_in[2];
    const float* A_log   = (const float*)d_in[3];
    const float* Dv      = (const float*)d_in[4];
    const float* W_out   = (const float*)d_in[5];
    float* out = (float*)d_out;

    float *dbc_p;
    __nv_bfloat16 *xh, *xl, *wh, *wl, *yh, *yl, *woh, *wol;
    cudaGetSymbolAddress((void**)&dbc_p, g_dbc);
    cudaGetSymbolAddress((void**)&xh, g_xh);
    cudaGetSymbolAddress((void**)&xl, g_xl);
    cudaGetSymbolAddress((void**)&wh, g_wh);
    cudaGetSymbolAddress((void**)&wl, g_wl);
    cudaGetSymbolAddress((void**)&yh, g_yh);
    cudaGetSymbolAddress((void**)&yl, g_yl);
    cudaGetSymbolAddress((void**)&woh, g_woh);
    cudaGetSymbolAddress((void**)&wol, g_wol);

    cudaFuncSetAttribute(gemm_mma, cudaFuncAttributeMaxDynamicSharedMemorySize,
                         SMEM_MMA_TOTAL);

    // 1) split conversions
    {
        size_t nx = (size_t)L_SEQ * DM;
        split_kernel<<<(unsigned)((nx / 4 + 255) / 256), 256>>>(x, xh, xl, nx, nx);
        size_t nwv = (size_t)PROJ * DM, nwt = (size_t)NPAD * DM;
        split_kernel<<<(unsigned)((nwt / 4 + 255) / 256), 256>>>(W_in, wh, wl, nwv, nwt);
        size_t nwo = (size_t)DM * DI;
        split_kernel<<<(unsigned)((nwo / 4 + 255) / 256), 256>>>(W_out, woh, wol, nwo, nwo);
    }
    // 2) dbc = x @ W_in^T  (tensor cores, split-bf16)
    {
        dim3 grid(L_SEQ / BM, NPAD / BN);     // 8 x 257
        gemm_mma<<<grid, 256, SMEM_MMA_TOTAL>>>(xh, xl, wh, wl, dbc_p, PROJ, PROJ);
    }
    // 3) delta
    {
        dim3 grid(L_SEQ / 8, DI / 128);
        delta_kernel<<<grid, 128>>>(W_delta);
    }
    // 4) scan (writes split y directly)
    scan_kernel<<<128, 128>>>(x, A_log, Dv);
    // 5) out = y @ W_out^T (tensor cores)
    {
        dim3 grid(L_SEQ / BM, DM / BN);       // 8 x 8
        gemm_mma<<<grid, 256, SMEM_MMA_TOTAL>>>(yh, yl, woh, wol, out, DM, DM);
    }
}

// round 7
// speedup vs baseline: 1.9563x; 1.9563x over previous
#include <cuda_runtime.h>
#include <cuda_bf16.h>
#include <cuda_fp16.h>
#include <math.h>
#include <stdint.h>

// Problem constants
#define L_SEQ   2048
#define DM      1024
#define DI      1024
#define DTR     64
#define DS      16
#define PROJ    (DTR + 2 * DI * DS)   // 32832
#define NPAD    32896                 // 257 * 128
#define KDIM    1024

// -------- scratch (static device globals; no allocation) --------
__device__ float g_dbc[(size_t)L_SEQ * PROJ];       // B/C (+unused delta cols)
__device__ float g_dlr[(size_t)L_SEQ * DTR];        // accurate delta_lr
__device__ float g_delta[(size_t)L_SEQ * DI];
__device__ __half g_xf[(size_t)L_SEQ * DM];
__device__ __half g_wf[(size_t)NPAD * DM];
__device__ __nv_bfloat16 g_xh[(size_t)L_SEQ * DM];
__device__ __nv_bfloat16 g_xl[(size_t)L_SEQ * DM];
__device__ __nv_bfloat16 g_wdh[(size_t)128 * DM];   // W_in rows 0..63, padded to 128
__device__ __nv_bfloat16 g_wdl[(size_t)128 * DM];
__device__ __nv_bfloat16 g_yh[(size_t)L_SEQ * DI];
__device__ __nv_bfloat16 g_yl[(size_t)L_SEQ * DI];
__device__ __nv_bfloat16 g_woh[(size_t)DM * DI];
__device__ __nv_bfloat16 g_wol[(size_t)DM * DI];

// ============================================================================
// helpers
// ============================================================================
__device__ __forceinline__ uint32_t smem_u32(const void* p) {
    uint32_t a;
    asm("{ .reg .u64 t; cvta.to.shared.u64 t, %1; cvt.u32.u64 %0, t; }" : "=r"(a) : "l"(p));
    return a;
}
__device__ __forceinline__ uint32_t swz128(uint32_t o) { return o ^ ((o >> 3) & 0x70); }

__device__ __forceinline__ void cp_async16(uint32_t dst, const void* src) {
    asm volatile("cp.async.cg.shared.global [%0], [%1], 16;" :: "r"(dst), "l"(src));
}
#define CP_COMMIT() asm volatile("cp.async.commit_group;" ::: "memory")
#define CP_WAIT(n)  asm volatile("cp.async.wait_group %0;" :: "n"(n) : "memory")

__device__ __forceinline__ void ldsm4(uint32_t* r, uint32_t addr) {
    asm volatile("ldmatrix.sync.aligned.m8n8.x4.shared.b16 {%0,%1,%2,%3}, [%4];"
        : "=r"(r[0]), "=r"(r[1]), "=r"(r[2]), "=r"(r[3]) : "r"(addr));
}
__device__ __forceinline__ void mma_bf16(float* d, const uint32_t* a, const uint32_t* b) {
    asm volatile(
        "mma.sync.aligned.m16n8k16.row.col.f32.bf16.bf16.f32 "
        "{%0,%1,%2,%3}, {%4,%5,%6,%7}, {%8,%9}, {%0,%1,%2,%3};"
        : "+f"(d[0]), "+f"(d[1]), "+f"(d[2]), "+f"(d[3])
        : "r"(a[0]), "r"(a[1]), "r"(a[2]), "r"(a[3]), "r"(b[0]), "r"(b[1]));
}
__device__ __forceinline__ void mma_f16(float* d, const uint32_t* a, const uint32_t* b) {
    asm volatile(
        "mma.sync.aligned.m16n8k16.row.col.f32.f16.f16.f32 "
        "{%0,%1,%2,%3}, {%4,%5,%6,%7}, {%8,%9}, {%0,%1,%2,%3};"
        : "+f"(d[0]), "+f"(d[1]), "+f"(d[2]), "+f"(d[3])
        : "r"(a[0]), "r"(a[1]), "r"(a[2]), "r"(a[3]), "r"(b[0]), "r"(b[1]));
}

// ============================================================================
// Conversions
// ============================================================================
__global__ __launch_bounds__(256) void cvt16_kernel(
    const float* __restrict__ src, __half* __restrict__ dst,
    size_t n_valid, size_t n_total)
{
    size_t i = ((size_t)blockIdx.x * 256 + threadIdx.x) * 4;
    if (i >= n_total) return;
    float4 v = make_float4(0.f, 0.f, 0.f, 0.f);
    if (i < n_valid) v = *(const float4*)(src + i);
    __half2 a = __floats2half2_rn(v.x, v.y);
    __half2 b = __floats2half2_rn(v.z, v.w);
    *(__half2*)(dst + i)     = a;
    *(__half2*)(dst + i + 2) = b;
}

__global__ __launch_bounds__(256) void split_kernel(
    const float* __restrict__ src, __nv_bfloat16* __restrict__ hi,
    __nv_bfloat16* __restrict__ lo, size_t n_valid, size_t n_total)
{
    size_t i = ((size_t)blockIdx.x * 256 + threadIdx.x) * 4;
    if (i >= n_total) return;
    float4 v = make_float4(0.f, 0.f, 0.f, 0.f);
    if (i < n_valid) v = *(const float4*)(src + i);
    __nv_bfloat16 h0 = __float2bfloat16_rn(v.x);
    __nv_bfloat16 h1 = __float2bfloat16_rn(v.y);
    __nv_bfloat16 h2 = __float2bfloat16_rn(v.z);
    __nv_bfloat16 h3 = __float2bfloat16_rn(v.w);
    __nv_bfloat16 l0 = __float2bfloat16_rn(v.x - __bfloat162float(h0));
    __nv_bfloat16 l1 = __float2bfloat16_rn(v.y - __bfloat162float(h1));
    __nv_bfloat16 l2 = __float2bfloat16_rn(v.z - __bfloat162float(h2));
    __nv_bfloat16 l3 = __float2bfloat16_rn(v.w - __bfloat162float(h3));
    *(__nv_bfloat162*)(hi + i)     = __nv_bfloat162(h0, h1);
    *(__nv_bfloat162*)(hi + i + 2) = __nv_bfloat162(h2, h3);
    *(__nv_bfloat162*)(lo + i)     = __nv_bfloat162(l0, l1);
    *(__nv_bfloat162*)(lo + i + 2) = __nv_bfloat162(l2, l3);
}

// ============================================================================
// FP16 1-product GEMM (for B/C columns): C[m,n] = A[m,:]·B[n,:]
// CTA 128x128, BK=64, 256 threads (8 warps 2x4, warp tile 64x32),
// 3-stage cp.async pipeline (32 KB/stage), 16 k-iters.
// ============================================================================
#define F_ATILE  16384              // 128 rows x 128 B
#define F_STAGE  32768              // A + B
#define F_NSTAGE 3
#define SMEM_F16_TOTAL (F_NSTAGE * F_STAGE)   // 96 KB
#define F_NKC    (KDIM / 64)        // 16

__global__ __launch_bounds__(256, 2) void gemm_f16(
    const __half* __restrict__ A, const __half* __restrict__ B,
    float* __restrict__ C, int ldc, int nvalid)
{
    extern __shared__ char smem[];
    const uint32_t sbase = smem_u32(smem);
    const int tid = threadIdx.x;
    const int wid = tid >> 5, lane = tid & 31;
    const int wm = wid & 1, wn = wid >> 1;       // 2 (m) x 4 (n)

    const int m0 = blockIdx.x * 128;
    const int n0 = blockIdx.y * 128;

    float acc[4][4][4];
    #pragma unroll
    for (int i = 0; i < 4; i++)
        #pragma unroll
        for (int j = 0; j < 4; j++)
            #pragma unroll
            for (int q = 0; q < 4; q++) acc[i][j][q] = 0.f;

    auto issue = [&](int kc) {
        if (kc < F_NKC) {
            const uint32_t soff = sbase + (kc % F_NSTAGE) * F_STAGE;
            #pragma unroll
            for (int j = 0; j < 4; j++) {
                const int q = tid * 4 + j;          // 0..1023
                const int row = q >> 3, c = q & 7;
                const uint32_t so = swz128((uint32_t)(row * 128 + c * 16));
                const size_t ga = (size_t)(m0 + row) * KDIM + (size_t)kc * 64 + c * 8;
                const size_t gb = (size_t)(n0 + row) * KDIM + (size_t)kc * 64 + c * 8;
                cp_async16(soff + so, A + ga);
                cp_async16(soff + F_ATILE + so, B + gb);
            }
        }
        CP_COMMIT();
    };

    issue(0);
    issue(1);

    #pragma unroll 1
    for (int kc = 0; kc < F_NKC; kc++) {
        if (kc + 1 < F_NKC) CP_WAIT(1); else CP_WAIT(0);
        __syncthreads();
        issue(kc + 2);

        const uint32_t sA = sbase + (kc % F_NSTAGE) * F_STAGE;

        #pragma unroll
        for (int ks = 0; ks < 4; ks++) {
            uint32_t bf[4][2];
            #pragma unroll
            for (int p = 0; p < 2; p++) {
                const int rowb = wn * 32 + p * 16 + ((lane >> 4) << 3) + (lane & 7);
                const int chb  = ks * 2 + ((lane >> 3) & 1);
                const uint32_t ob = swz128((uint32_t)(rowb * 128 + chb * 16));
                ldsm4(&bf[p * 2][0], sA + F_ATILE + ob);
            }
            #pragma unroll
            for (int mf = 0; mf < 4; mf++) {
                const int rowa = wm * 64 + mf * 16 + (lane & 15);
                const int cha  = ks * 2 + (lane >> 4);
                const uint32_t oa = swz128((uint32_t)(rowa * 128 + cha * 16));
                uint32_t af[4];
                ldsm4(af, sA + oa);
                #pragma unroll
                for (int nf = 0; nf < 4; nf++) mma_f16(acc[mf][nf], af, bf[nf]);
            }
        }
    }

    const int g = lane >> 2, t4 = lane & 3;
    #pragma unroll
    for (int mf = 0; mf < 4; mf++) {
        #pragma unroll
        for (int nf = 0; nf < 4; nf++) {
            const int m = m0 + wm * 64 + mf * 16 + g;
            const int n = n0 + wn * 32 + nf * 8 + t4 * 2;
            if (n < nvalid) {
                *(float2*)(C + (size_t)m * ldc + n) =
                    make_float2(acc[mf][nf][0], acc[mf][nf][1]);
                *(float2*)(C + (size_t)(m + 8) * ldc + n) =
                    make_float2(acc[mf][nf][2], acc[mf][nf][3]);
            }
        }
    }
}

// ============================================================================
// Split-bf16 (3-product) GEMM — accurate path for delta_lr and out-proj.
// CTA 128x128, BK=32, 3-stage pipeline. (R5 structure)
// ============================================================================
#define GTILE   8192
#define STAGE_B (4 * GTILE)
#define NSTAGE  3
#define SMEM_MMA_TOTAL (NSTAGE * STAGE_B)    // 96 KB
#define NKC     (KDIM / 32)

__global__ __launch_bounds__(256, 2) void gemm_mma(
    const __nv_bfloat16* __restrict__ Ah, const __nv_bfloat16* __restrict__ Al,
    const __nv_bfloat16* __restrict__ Bh, const __nv_bfloat16* __restrict__ Bl,
    float* __restrict__ C, int ldc, int nvalid)
{
    extern __shared__ char smem[];
    const uint32_t sbase = smem_u32(smem);
    const int tid = threadIdx.x;
    const int wid = tid >> 5, lane = tid & 31;
    const int wm = wid & 1, wn = wid >> 1;

    const int m0 = blockIdx.x * 128;
    const int n0 = blockIdx.y * 128;

    float acc[4][4][4];
    #pragma unroll
    for (int i = 0; i < 4; i++)
        #pragma unroll
        for (int j = 0; j < 4; j++)
            #pragma unroll
            for (int q = 0; q < 4; q++) acc[i][j][q] = 0.f;

    const int q0 = tid * 2;

    auto issue = [&](int kc) {
        if (kc < NKC) {
            const uint32_t soff = sbase + (kc % NSTAGE) * STAGE_B;
            #pragma unroll
            for (int j = 0; j < 2; j++) {
                const int q = q0 + j;
                const int row = q >> 2, c = q & 3;
                const uint32_t so = swz128((uint32_t)(row * 64 + c * 16));
                const size_t gk = (size_t)kc * 32 + c * 8;
                const size_t ga = (size_t)(m0 + row) * KDIM + gk;
                const size_t gb = (size_t)(n0 + row) * KDIM + gk;
                cp_async16(soff + 0 * GTILE + so, Ah + ga);
                cp_async16(soff + 1 * GTILE + so, Al + ga);
                cp_async16(soff + 2 * GTILE + so, Bh + gb);
                cp_async16(soff + 3 * GTILE + so, Bl + gb);
            }
        }
        CP_COMMIT();
    };

    issue(0);
    issue(1);

    #pragma unroll 1
    for (int kc = 0; kc < NKC; kc++) {
        if (kc + 1 < NKC) CP_WAIT(1); else CP_WAIT(0);
        __syncthreads();
        issue(kc + 2);

        const uint32_t sA = sbase + (kc % NSTAGE) * STAGE_B;

        #pragma unroll
        for (int ks = 0; ks < 2; ks++) {
            uint32_t bh[4][2], bl[4][2];
            #pragma unroll
            for (int p = 0; p < 2; p++) {
                const int rowb = wn * 32 + p * 16 + ((lane >> 4) << 3) + (lane & 7);
                const int chb  = ks * 2 + ((lane >> 3) & 1);
                const uint32_t ob = swz128((uint32_t)(rowb * 64 + chb * 16));
                ldsm4(&bh[p * 2][0], sA + 2 * GTILE + ob);
                ldsm4(&bl[p * 2][0], sA + 3 * GTILE + ob);
            }
            #pragma unroll
            for (int mf = 0; mf < 4; mf++) {
                const int rowa = wm * 64 + mf * 16 + (lane & 15);
                const int cha  = ks * 2 + (lane >> 4);
                const uint32_t oa = swz128((uint32_t)(rowa * 64 + cha * 16));
                uint32_t ah[4], al[4];
                ldsm4(ah, sA + 0 * GTILE + oa);
                ldsm4(al, sA + 1 * GTILE + oa);
                #pragma unroll
                for (int nf = 0; nf < 4; nf++) mma_bf16(acc[mf][nf], ah, bh[nf]);
                #pragma unroll
                for (int nf = 0; nf < 4; nf++) mma_bf16(acc[mf][nf], al, bh[nf]);
                #pragma unroll
                for (int nf = 0; nf < 4; nf++) mma_bf16(acc[mf][nf], ah, bl[nf]);
            }
        }
    }

    const int g = lane >> 2, t4 = lane & 3;
    #pragma unroll
    for (int mf = 0; mf < 4; mf++) {
        #pragma unroll
        for (int nf = 0; nf < 4; nf++) {
            const int m = m0 + wm * 64 + mf * 16 + g;
            const int n = n0 + wn * 32 + nf * 8 + t4 * 2;
            if (n < nvalid) {
                *(float2*)(C + (size_t)m * ldc + n) =
                    make_float2(acc[mf][nf][0], acc[mf][nf][1]);
                *(float2*)(C + (size_t)(m + 8) * ldc + n) =
                    make_float2(acc[mf][nf][2], acc[mf][nf][3]);
            }
        }
    }
}

// ============================================================================
// delta[t,d] = softplus(g_dlr[t,:] · W_delta[d,:])
// ============================================================================
__global__ __launch_bounds__(128) void delta_kernel(const float* __restrict__ W_delta)
{
    __shared__ float s_dl[8][64];
    __shared__ float s_wT[64][129];
    const int tid = threadIdx.x;
    const int t0 = blockIdx.x * 8;
    const int d0 = blockIdx.y * 128;

    for (int i = tid; i < 8 * 64; i += 128) {
        int t = i >> 6, k = i & 63;
        s_dl[t][k] = g_dlr[(size_t)(t0 + t) * DTR + k];
    }
    for (int i = tid; i < 128 * 64; i += 128) {
        int d = i >> 6, k = i & 63;
        s_wT[k][d] = W_delta[(size_t)(d0 + d) * DTR + k];
    }
    __syncthreads();

    float accv[8];
    #pragma unroll
    for (int t = 0; t < 8; t++) accv[t] = 0.f;
    #pragma unroll 8
    for (int k = 0; k < 64; k++) {
        float w = s_wT[k][tid];
        #pragma unroll
        for (int t = 0; t < 8; t++) accv[t] = fmaf(s_dl[t][k], w, accv[t]);
    }
    #pragma unroll
    for (int t = 0; t < 8; t++) {
        float z = accv[t];
        float sp = fmaxf(z, 0.f) + log1pf(__expf(-fabsf(z)));
        g_delta[(size_t)(t0 + t) * DI + d0 + tid] = sp;
    }
}

// ============================================================================
// Selective scan: 1 thread per (d, s). 128 blocks x 128 threads, prefetch 8.
// Writes y directly as split bf16 (yh, yl).
// ============================================================================
__global__ __launch_bounds__(128) void scan_kernel(
    const float* __restrict__ x, const float* __restrict__ A_log,
    const float* __restrict__ Dv)
{
    const int g = blockIdx.x * 128 + threadIdx.x;
    const int d = g >> 4, s = g & 15;
    const float a = -expf(A_log[d * DS + s]);
    const float Dd = Dv[d];
    const float* bp = g_dbc + DTR + d * DS + s;
    const float* cp = bp + DI * DS;

    float Bpf[8], Cpf[8], Tpf[8], Xpf[8];
    #pragma unroll
    for (int i = 0; i < 8; i++) {
        Bpf[i] = bp[(size_t)i * PROJ];
        Cpf[i] = cp[(size_t)i * PROJ];
        Tpf[i] = g_delta[(size_t)i * DI + d];
        Xpf[i] = x[(size_t)i * DI + d];
    }
    float h = 0.f;
    #pragma unroll 8
    for (int t = 0; t < L_SEQ; t++) {
        const int sl = t & 7;
        const float dt = Tpf[sl], xt = Xpf[sl], Bv = Bpf[sl], Cv = Cpf[sl];
        const int tn = t + 8;
        if (tn < L_SEQ) {
            Bpf[sl] = bp[(size_t)tn * PROJ];
            Cpf[sl] = cp[(size_t)tn * PROJ];
            Tpf[sl] = g_delta[(size_t)tn * DI + d];
            Xpf[sl] = x[(size_t)tn * DI + d];
        }
        h = fmaf(__expf(dt * a), h, dt * xt * Bv);
        float yv = h * Cv;
        yv += __shfl_xor_sync(0xffffffffu, yv, 1);
        yv += __shfl_xor_sync(0xffffffffu, yv, 2);
        yv += __shfl_xor_sync(0xffffffffu, yv, 4);
        yv += __shfl_xor_sync(0xffffffffu, yv, 8);
        if (s == 0) {
            float yfull = fmaf(xt, Dd, yv);
            __nv_bfloat16 yh = __float2bfloat16_rn(yfull);
            __nv_bfloat16 yl = __float2bfloat16_rn(yfull - __bfloat162float(yh));
            g_yh[(size_t)t * DI + d] = yh;
            g_yl[(size_t)t * DI + d] = yl;
        }
    }
}

// ============================================================================
// Launch
// ============================================================================
extern "C" void kernel_launch(void* const* d_in, const int* in_sizes, int n_in,
                              void* d_out, int out_size)
{
    const float* x       = (const float*)d_in[0];
    const float* W_in    = (const float*)d_in[1];
    const float* W_delta = (const float*)d_in[2];
    const float* A_log   = (const float*)d_in[3];
    const float* Dv      = (const float*)d_in[4];
    const float* W_out   = (const float*)d_in[5];
    float* out = (float*)d_out;

    float *dbc_p, *dlr_p;
    __half *xf, *wf;
    __nv_bfloat16 *xh, *xl, *wdh, *wdl, *yh, *yl, *woh, *wol;
    cudaGetSymbolAddress((void**)&dbc_p, g_dbc);
    cudaGetSymbolAddress((void**)&dlr_p, g_dlr);
    cudaGetSymbolAddress((void**)&xf, g_xf);
    cudaGetSymbolAddress((void**)&wf, g_wf);
    cudaGetSymbolAddress((void**)&xh, g_xh);
    cudaGetSymbolAddress((void**)&xl, g_xl);
    cudaGetSymbolAddress((void**)&wdh, g_wdh);
    cudaGetSymbolAddress((void**)&wdl, g_wdl);
    cudaGetSymbolAddress((void**)&yh, g_yh);
    cudaGetSymbolAddress((void**)&yl, g_yl);
    cudaGetSymbolAddress((void**)&woh, g_woh);
    cudaGetSymbolAddress((void**)&wol, g_wol);

    cudaFuncSetAttribute(gemm_f16, cudaFuncAttributeMaxDynamicSharedMemorySize,
                         SMEM_F16_TOTAL);
    cudaFuncSetAttribute(gemm_mma, cudaFuncAttributeMaxDynamicSharedMemorySize,
                         SMEM_MMA_TOTAL);

    // 1) conversions
    {
        size_t nx = (size_t)L_SEQ * DM;
        cvt16_kernel<<<(unsigned)((nx / 4 + 255) / 256), 256>>>(x, xf, nx, nx);
        size_t nwv = (size_t)PROJ * DM, nwt = (size_t)NPAD * DM;
        cvt16_kernel<<<(unsigned)((nwt / 4 + 255) / 256), 256>>>(W_in, wf, nwv, nwt);
        split_kernel<<<(unsigned)((nx / 4 + 255) / 256), 256>>>(x, xh, xl, nx, nx);
        size_t nwd_v = (size_t)DTR * DM, nwd_t = (size_t)128 * DM;
        split_kernel<<<(unsigned)((nwd_t / 4 + 255) / 256), 256>>>(W_in, wdh, wdl, nwd_v, nwd_t);
        size_t nwo = (size_t)DM * DI;
        split_kernel<<<(unsigned)((nwo / 4 + 255) / 256), 256>>>(W_out, woh, wol, nwo, nwo);
    }
    // 2) dbc (B/C cols) = x @ W_in^T  via fp16 tensor cores
    {
        dim3 grid(L_SEQ / 128, NPAD / 128);   // 16 x 257
        gemm_f16<<<grid, 256, SMEM_F16_TOTAL>>>(xf, wf, dbc_p, PROJ, PROJ);
    }
    // 3) accurate delta_lr = x @ W_in[0:64]^T  via bf16x3
    {
        dim3 grid(L_SEQ / 128, 1);
        gemm_mma<<<grid, 256, SMEM_MMA_TOTAL>>>(xh, xl, wdh, wdl, dlr_p, DTR, DTR);
    }
    // 4) delta
    {
        dim3 grid(L_SEQ / 8, DI / 128);
        delta_kernel<<<grid, 128>>>(W_delta);
    }
    // 5) scan (writes split y directly)
    scan_kernel<<<128, 128>>>(x, A_log, Dv);
    // 6) out = y @ W_out^T via bf16x3
    {
        dim3 grid(L_SEQ / 128, DM / 128);
        gemm_mma<<<grid, 256, SMEM_MMA_TOTAL>>>(yh, yl, woh, wol, out, DM, DM);
    }
}